// round 1
// baseline (speedup 1.0000x reference)
#include <cuda_runtime.h>
#include <math.h>

#define C_DIM 512
#define B_DIM 64
#define N_DIM 1024
#define M_AG  16
#define R_DIM (B_DIM * N_DIM)   // 65536

// ---------------- scratch (allocation-free) ----------------
__device__ float g_Q[(size_t)R_DIM * C_DIM];
__device__ float g_K[(size_t)R_DIM * C_DIM];
__device__ float g_V[(size_t)R_DIM * C_DIM];
__device__ float g_A[(size_t)B_DIM * M_AG * C_DIM];
__device__ float g_AF[(size_t)B_DIM * M_AG * C_DIM];
__device__ float g_Attn[(size_t)R_DIM * C_DIM];

// ---------------- GEMM: Y[r,n] = sum_k X[r,k] * W[n,k] + bias[n] ----------------
// X: [R,K] row-major, W: [N,K] row-major (nn.Linear weight), Y: [R,N]
#define BM 128
#define BN 128
#define BK 16
#define SPAD 4

__global__ __launch_bounds__(256, 2)
void sgemm_nt_bias(const float* __restrict__ X, const float* __restrict__ W,
                   const float* __restrict__ bias, float* __restrict__ Y,
                   int R, int N, int K)
{
    __shared__ float Xs[BK][BM + SPAD];
    __shared__ float Ws[BK][BN + SPAD];

    const int tid = threadIdx.x;
    const int tx  = tid & 15;   // n direction (16)
    const int ty  = tid >> 4;   // m direction (16)
    const int r0  = blockIdx.y * BM;
    const int n0  = blockIdx.x * BN;

    float acc[8][8];
#pragma unroll
    for (int i = 0; i < 8; i++)
#pragma unroll
        for (int j = 0; j < 8; j++) acc[i][j] = 0.f;

    const int lrow = tid >> 2;          // 0..63
    const int lkc  = (tid & 3) * 4;     // 0,4,8,12

    for (int k0 = 0; k0 < K; k0 += BK) {
#pragma unroll
        for (int h = 0; h < 2; h++) {
            int row = lrow + h * 64;
            float4 v = *reinterpret_cast<const float4*>(&X[(size_t)(r0 + row) * K + k0 + lkc]);
            Xs[lkc + 0][row] = v.x; Xs[lkc + 1][row] = v.y;
            Xs[lkc + 2][row] = v.z; Xs[lkc + 3][row] = v.w;
            float4 w = *reinterpret_cast<const float4*>(&W[(size_t)(n0 + row) * K + k0 + lkc]);
            Ws[lkc + 0][row] = w.x; Ws[lkc + 1][row] = w.y;
            Ws[lkc + 2][row] = w.z; Ws[lkc + 3][row] = w.w;
        }
        __syncthreads();
#pragma unroll
        for (int k = 0; k < BK; k++) {
            float a[8], b[8];
#pragma unroll
            for (int i = 0; i < 8; i++) a[i] = Xs[k][ty * 8 + i];
#pragma unroll
            for (int j = 0; j < 8; j++) b[j] = Ws[k][tx * 8 + j];
#pragma unroll
            for (int i = 0; i < 8; i++)
#pragma unroll
                for (int j = 0; j < 8; j++)
                    acc[i][j] = fmaf(a[i], b[j], acc[i][j]);
        }
        __syncthreads();
    }

    float bb[8];
#pragma unroll
    for (int j = 0; j < 8; j++) bb[j] = bias[n0 + tx * 8 + j];
#pragma unroll
    for (int i = 0; i < 8; i++) {
        int r = r0 + ty * 8 + i;
#pragma unroll
        for (int j = 0; j < 8; j++)
            Y[(size_t)r * N + n0 + tx * 8 + j] = acc[i][j] + bb[j];
    }
}

// ---------------- pooling: A[bm,c] = mean_{t<64} Q[bm*64 + t, c] ----------------
__global__ void pool_kernel(const float* __restrict__ Q, float* __restrict__ A)
{
    int bm = blockIdx.x;          // 0..B*M-1
    int c  = threadIdx.x;         // 0..511
    const float* base = Q + (size_t)bm * 64 * C_DIM + c;
    float s = 0.f;
#pragma unroll 8
    for (int t = 0; t < 64; t++) s += base[(size_t)t * C_DIM];
    A[(size_t)bm * C_DIM + c] = s * (1.0f / 64.0f);
}

// ---------------- agent features: AF[b,m,:] = softmax_n(scale * A[b,m]·K[b,n]) @ V[b] ----------------
__global__ __launch_bounds__(256)
void agent_features_kernel(const float* __restrict__ A, const float* __restrict__ Kmat,
                           const float* __restrict__ V, float* __restrict__ AF)
{
    __shared__ float a_s[C_DIM];
    __shared__ float p_s[N_DIM];
    __shared__ float red[256];

    const int bm  = blockIdx.x;   // b*16 + m
    const int b   = bm >> 4;
    const int tid = threadIdx.x;
    const float scale = rsqrtf((float)C_DIM);

    for (int c = tid; c < C_DIM; c += 256)
        a_s[c] = A[(size_t)bm * C_DIM + c];
    __syncthreads();

    const float* Kb = Kmat + (size_t)b * N_DIM * C_DIM;
#pragma unroll
    for (int i = 0; i < 4; i++) {
        int n = tid + i * 256;
        const float4* krow = reinterpret_cast<const float4*>(Kb + (size_t)n * C_DIM);
        float dot = 0.f;
#pragma unroll 4
        for (int c4 = 0; c4 < C_DIM / 4; c4++) {
            float4 kv = krow[c4];
            dot += a_s[c4 * 4 + 0] * kv.x + a_s[c4 * 4 + 1] * kv.y
                 + a_s[c4 * 4 + 2] * kv.z + a_s[c4 * 4 + 3] * kv.w;
        }
        p_s[n] = dot * scale;
    }
    __syncthreads();

    // block softmax over 1024
    float lmax = -INFINITY;
#pragma unroll
    for (int i = 0; i < 4; i++) lmax = fmaxf(lmax, p_s[tid + i * 256]);
    red[tid] = lmax; __syncthreads();
    for (int s = 128; s > 0; s >>= 1) {
        if (tid < s) red[tid] = fmaxf(red[tid], red[tid + s]);
        __syncthreads();
    }
    const float mx = red[0];
    __syncthreads();

    float lsum = 0.f;
#pragma unroll
    for (int i = 0; i < 4; i++) {
        int n = tid + i * 256;
        float e = __expf(p_s[n] - mx);
        p_s[n] = e;
        lsum += e;
    }
    red[tid] = lsum; __syncthreads();
    for (int s = 128; s > 0; s >>= 1) {
        if (tid < s) red[tid] += red[tid + s];
        __syncthreads();
    }
    const float inv = 1.0f / red[0];

    // AF[c] = inv * sum_n p_s[n] * V[b,n,c], two columns per thread (coalesced)
    const float* Vb = V + (size_t)b * N_DIM * C_DIM;
    float acc0 = 0.f, acc1 = 0.f;
    for (int n = 0; n < N_DIM; n++) {
        float p = p_s[n];
        const float* vrow = Vb + (size_t)n * C_DIM;
        acc0 = fmaf(p, vrow[tid],        acc0);
        acc1 = fmaf(p, vrow[tid + 256],  acc1);
    }
    AF[(size_t)bm * C_DIM + tid]       = acc0 * inv;
    AF[(size_t)bm * C_DIM + tid + 256] = acc1 * inv;
}

// ---------------- agent attn: Attn[b,n,:] = softmax_m(scale * Q[b,n]·A[b,m]) @ AF[b] ----------------
// one warp per token; 16 tokens per block; AF[b] cached in 32KB smem
__global__ __launch_bounds__(512)
void agent_attn_kernel(const float* __restrict__ Q, const float* __restrict__ A,
                       const float* __restrict__ AF, float* __restrict__ Attn)
{
    __shared__ float af_s[M_AG][C_DIM];   // 32 KB

    const int b    = blockIdx.y;
    const int n0   = blockIdx.x * 16;
    const int tid  = threadIdx.x;
    const int warp = tid >> 5;
    const int lane = tid & 31;
    const float scale = rsqrtf((float)C_DIM);

    const float* AFb = AF + (size_t)b * M_AG * C_DIM;
    for (int i = tid; i < M_AG * C_DIM; i += 512)
        (&af_s[0][0])[i] = AFb[i];
    __syncthreads();

    const int n = n0 + warp;
    const float* qrow = Q + ((size_t)b * N_DIM + n) * C_DIM;
    float q[16];
#pragma unroll
    for (int k = 0; k < 16; k++) q[k] = qrow[lane + 32 * k];

    const float* Ab = A + (size_t)b * M_AG * C_DIM;
    float lg[16];
#pragma unroll
    for (int m = 0; m < M_AG; m++) {
        const float* arow = Ab + (size_t)m * C_DIM;
        float p = 0.f;
#pragma unroll
        for (int k = 0; k < 16; k++) p = fmaf(q[k], arow[lane + 32 * k], p);
#pragma unroll
        for (int off = 16; off > 0; off >>= 1)
            p += __shfl_xor_sync(0xffffffffu, p, off);
        lg[m] = p * scale;
    }

    float mx = lg[0];
#pragma unroll
    for (int m = 1; m < M_AG; m++) mx = fmaxf(mx, lg[m]);
    float s = 0.f;
#pragma unroll
    for (int m = 0; m < M_AG; m++) { lg[m] = __expf(lg[m] - mx); s += lg[m]; }
    const float inv = 1.0f / s;

    float* orow = Attn + ((size_t)b * N_DIM + n) * C_DIM;
#pragma unroll
    for (int k = 0; k < 16; k++) {
        int c = lane + 32 * k;
        float o = 0.f;
#pragma unroll
        for (int m = 0; m < M_AG; m++) o = fmaf(lg[m], af_s[m][c], o);
        orow[c] = o * inv;
    }
}

// ---------------- launch ----------------
extern "C" void kernel_launch(void* const* d_in, const int* in_sizes, int n_in,
                              void* d_out, int out_size)
{
    const float* x  = (const float*)d_in[0];
    const float* Wq = (const float*)d_in[1];
    const float* bq = (const float*)d_in[2];
    const float* Wk = (const float*)d_in[3];
    const float* bk = (const float*)d_in[4];
    const float* Wv = (const float*)d_in[5];
    const float* bv = (const float*)d_in[6];
    const float* Wo = (const float*)d_in[7];
    const float* bo = (const float*)d_in[8];
    float* out = (float*)d_out;

    float *Q, *K, *V, *A, *AF, *At;
    cudaGetSymbolAddress((void**)&Q,  g_Q);
    cudaGetSymbolAddress((void**)&K,  g_K);
    cudaGetSymbolAddress((void**)&V,  g_V);
    cudaGetSymbolAddress((void**)&A,  g_A);
    cudaGetSymbolAddress((void**)&AF, g_AF);
    cudaGetSymbolAddress((void**)&At, g_Attn);

    dim3 gemm_grid(C_DIM / BN, R_DIM / BM);   // (4, 512)
    sgemm_nt_bias<<<gemm_grid, 256>>>(x, Wq, bq, Q, R_DIM, C_DIM, C_DIM);
    sgemm_nt_bias<<<gemm_grid, 256>>>(x, Wk, bk, K, R_DIM, C_DIM, C_DIM);
    sgemm_nt_bias<<<gemm_grid, 256>>>(x, Wv, bv, V, R_DIM, C_DIM, C_DIM);

    pool_kernel<<<B_DIM * M_AG, C_DIM>>>(Q, A);

    agent_features_kernel<<<B_DIM * M_AG, 256>>>(A, K, V, AF);

    dim3 attn_grid(N_DIM / 16, B_DIM);        // (64, 64)
    agent_attn_kernel<<<attn_grid, 512>>>(Q, A, AF, At);

    sgemm_nt_bias<<<gemm_grid, 256>>>(At, Wo, bo, out, R_DIM, C_DIM, C_DIM);
}

// round 3
// speedup vs baseline: 1.7515x; 1.7515x over previous
#include <cuda_runtime.h>
#include <cuda_bf16.h>
#include <math.h>
#include <stdint.h>

#define C_DIM 512
#define B_DIM 64
#define N_DIM 1024
#define M_AG  16
#define R_DIM (B_DIM * N_DIM)   // 65536
#define K2    1024               // combined hi|lo row length

// ---------------- scratch (allocation-free) ----------------
__device__ float g_Q[(size_t)R_DIM * C_DIM];
__device__ float g_K[(size_t)R_DIM * C_DIM];
__device__ float g_V[(size_t)R_DIM * C_DIM];
__device__ float g_A[(size_t)B_DIM * M_AG * C_DIM];
__device__ float g_AF[(size_t)B_DIM * M_AG * C_DIM];
__device__ __nv_bfloat16 g_Xs[(size_t)R_DIM * K2];     // [ hi(512) | lo(512) ]
__device__ __nv_bfloat16 g_Ats[(size_t)R_DIM * K2];
__device__ __nv_bfloat16 g_Ws[(size_t)4 * C_DIM * K2];

__device__ __forceinline__ uint32_t smem_u32(const void* p) {
    return (uint32_t)__cvta_generic_to_shared(p);
}
__device__ __forceinline__ void cp_async16(uint32_t s, const void* g) {
    asm volatile("cp.async.cg.shared.global [%0], [%1], 16;" :: "r"(s), "l"(g));
}
__device__ __forceinline__ void ldmatrix_x4(uint32_t* r, uint32_t addr) {
    asm volatile("ldmatrix.sync.aligned.m8n8.x4.shared.b16 {%0,%1,%2,%3}, [%4];"
                 : "=r"(r[0]), "=r"(r[1]), "=r"(r[2]), "=r"(r[3]) : "r"(addr));
}
__device__ __forceinline__ void mma16816(float* c, const uint32_t* a, uint32_t b0, uint32_t b1) {
    asm volatile(
        "mma.sync.aligned.m16n8k16.row.col.f32.bf16.bf16.f32 "
        "{%0,%1,%2,%3}, {%4,%5,%6,%7}, {%8,%9}, {%0,%1,%2,%3};"
        : "+f"(c[0]), "+f"(c[1]), "+f"(c[2]), "+f"(c[3])
        : "r"(a[0]), "r"(a[1]), "r"(a[2]), "r"(a[3]), "r"(b0), "r"(b1));
}

// ================= fp32 -> bf16 hi/lo split (combined [hi|lo] layout) =================
// src rows of 512 fp32; dst rows of 1024 bf16: [0,512)=hi, [512,1024)=lo
__global__ void split_kernel(const float* __restrict__ src, __nv_bfloat16* __restrict__ dst, int nq)
{
    int i = blockIdx.x * blockDim.x + threadIdx.x;
    if (i >= nq) return;
    int row = i >> 7;          // 128 float4 per 512-row
    int c4  = i & 127;
    float4 v = reinterpret_cast<const float4*>(src)[i];
    __nv_bfloat16 h0 = __float2bfloat16(v.x), h1 = __float2bfloat16(v.y);
    __nv_bfloat16 h2 = __float2bfloat16(v.z), h3 = __float2bfloat16(v.w);
    __nv_bfloat16 l0 = __float2bfloat16(v.x - __bfloat162float(h0));
    __nv_bfloat16 l1 = __float2bfloat16(v.y - __bfloat162float(h1));
    __nv_bfloat16 l2 = __float2bfloat16(v.z - __bfloat162float(h2));
    __nv_bfloat16 l3 = __float2bfloat16(v.w - __bfloat162float(h3));
    uint2 ph, pl;
    ph.x = (uint32_t)__bfloat16_as_ushort(h0) | ((uint32_t)__bfloat16_as_ushort(h1) << 16);
    ph.y = (uint32_t)__bfloat16_as_ushort(h2) | ((uint32_t)__bfloat16_as_ushort(h3) << 16);
    pl.x = (uint32_t)__bfloat16_as_ushort(l0) | ((uint32_t)__bfloat16_as_ushort(l1) << 16);
    pl.y = (uint32_t)__bfloat16_as_ushort(l2) | ((uint32_t)__bfloat16_as_ushort(l3) << 16);
    *reinterpret_cast<uint2*>(dst + (size_t)row * K2 + c4 * 4)       = ph;
    *reinterpret_cast<uint2*>(dst + (size_t)row * K2 + 512 + c4 * 4) = pl;
}

// ================= mma.sync bf16 split GEMM =================
// Y[r,n] = sum over 3 terms of Xterm[r,:]·Wterm[n,:] + bias[n]
// CTA tile 128x128, BK=64 bf16, 3-stage cp.async pipeline, 8 warps (4x2), warp tile 32x64.
#define GITERS  24      // 1536 / 64
#define GSTAGES 3
#define STG_BYTES 32768 // X tile 16KB + W tile 16KB
#define GEMM_SMEM (GSTAGES * STG_BYTES)

__global__ __launch_bounds__(256, 2)
void gemm_mma(const __nv_bfloat16* __restrict__ Xs, const __nv_bfloat16* __restrict__ Ws,
              const float* __restrict__ bias, float* __restrict__ Y)
{
    extern __shared__ char smem[];
    const uint32_t sb = smem_u32(smem);
    const int t   = threadIdx.x;
    const int L   = t & 31;
    const int wid = t >> 5;
    const int r0  = blockIdx.y * 128;
    const int n0  = blockIdx.x * 128;
    const int wm  = (wid & 3) * 32;
    const int wn  = (wid >> 2) * 64;

    // cp.async mapping: thread -> (row, 4 chunks of 16B); 8 chunks (128B) per row
    const int ldrow   = t >> 1;
    const int ldchunk = (t & 1) * 4;
    const uint32_t ld_mask = (uint32_t)(ldrow & 7) << 4;

    float acc[2][8][4];
#pragma unroll
    for (int m = 0; m < 2; m++)
#pragma unroll
        for (int n = 0; n < 8; n++)
#pragma unroll
            for (int k = 0; k < 4; k++) acc[m][n][k] = 0.f;

#define LOAD_STAGE(I)                                                                     \
    do {                                                                                  \
        const int s_   = (I) % GSTAGES;                                                   \
        const int kk_  = ((I) & 7) * 64;                                                  \
        const int xo_  = kk_ + (((I) >= 16) ? 512 : 0);                                   \
        const int wo_  = kk_ + (((I) >= 8 && (I) < 16) ? 512 : 0);                        \
        const __nv_bfloat16* gx_ = Xs + (size_t)(r0 + ldrow) * K2 + xo_ + ldchunk * 8;    \
        const __nv_bfloat16* gw_ = Ws + (size_t)(n0 + ldrow) * K2 + wo_ + ldchunk * 8;    \
        const uint32_t base_ = sb + s_ * STG_BYTES;                                       \
        _Pragma("unroll")                                                                 \
        for (int j = 0; j < 4; j++) {                                                     \
            uint32_t o_ = (uint32_t)(ldrow * 128 + (ldchunk + j) * 16) ^ ld_mask;         \
            cp_async16(base_ + o_,         gx_ + j * 8);                                  \
            cp_async16(base_ + 16384 + o_, gw_ + j * 8);                                  \
        }                                                                                 \
        asm volatile("cp.async.commit_group;" ::: "memory");                              \
    } while (0)

    LOAD_STAGE(0);
    LOAD_STAGE(1);

    // precompute per-lane ldmatrix row/base info
    const int a_row0 = wm + (L & 15);           // + mt*16
    const int a_colx = ((L >> 4) & 1) * 16;     // + ks*32
    const int b_row0 = wn + (L & 7) + ((L >> 4) & 1) * 8;  // + p*16
    const int b_colx = ((L >> 3) & 1) * 16;

#pragma unroll 1
    for (int i = 0; i < GITERS; i++) {
        if (i < GITERS - 1)
            asm volatile("cp.async.wait_group 1;" ::: "memory");
        else
            asm volatile("cp.async.wait_group 0;" ::: "memory");
        __syncthreads();

        if (i + 2 < GITERS) LOAD_STAGE(i + 2);

        const uint32_t stX = sb + (i % GSTAGES) * STG_BYTES;
        const uint32_t stW = stX + 16384;

#pragma unroll
        for (int ks = 0; ks < 4; ks++) {
            uint32_t a[2][4];
#pragma unroll
            for (int mt = 0; mt < 2; mt++) {
                int row = a_row0 + mt * 16;
                uint32_t off = (uint32_t)(row * 128 + ks * 32 + a_colx);
                off ^= (uint32_t)(row & 7) << 4;
                ldmatrix_x4(a[mt], stX + off);
            }
            uint32_t bf[4][4];
#pragma unroll
            for (int p = 0; p < 4; p++) {
                int rn = b_row0 + p * 16;
                uint32_t off = (uint32_t)(rn * 128 + ks * 32 + b_colx);
                off ^= (uint32_t)(rn & 7) << 4;
                ldmatrix_x4(bf[p], stW + off);
            }
#pragma unroll
            for (int mt = 0; mt < 2; mt++)
#pragma unroll
                for (int nt = 0; nt < 8; nt++)
                    mma16816(acc[mt][nt], a[mt], bf[nt >> 1][(nt & 1) * 2], bf[nt >> 1][(nt & 1) * 2 + 1]);
        }
    }

    // epilogue
    const int g  = L >> 2;
    const int cq = (L & 3) * 2;
#pragma unroll
    for (int mt = 0; mt < 2; mt++) {
        const int r = r0 + wm + mt * 16 + g;
#pragma unroll
        for (int nt = 0; nt < 8; nt++) {
            const int col = n0 + wn + nt * 8 + cq;
            const float b0 = __ldg(&bias[col]);
            const float b1 = __ldg(&bias[col + 1]);
            float2 o0 = make_float2(acc[mt][nt][0] + b0, acc[mt][nt][1] + b1);
            float2 o1 = make_float2(acc[mt][nt][2] + b0, acc[mt][nt][3] + b1);
            *reinterpret_cast<float2*>(Y + (size_t)r * C_DIM + col)       = o0;
            *reinterpret_cast<float2*>(Y + (size_t)(r + 8) * C_DIM + col) = o1;
        }
    }
#undef LOAD_STAGE
}

// ---------------- pooling ----------------
__global__ void pool_kernel(const float* __restrict__ Q, float* __restrict__ A)
{
    int bm = blockIdx.x;
    int c  = threadIdx.x;
    const float* base = Q + (size_t)bm * 64 * C_DIM + c;
    float s = 0.f;
#pragma unroll 8
    for (int t = 0; t < 64; t++) s += base[(size_t)t * C_DIM];
    A[(size_t)bm * C_DIM + c] = s * (1.0f / 64.0f);
}

// ---------------- agent features ----------------
__global__ __launch_bounds__(256)
void agent_features_kernel(const float* __restrict__ A, const float* __restrict__ Kmat,
                           const float* __restrict__ V, float* __restrict__ AF)
{
    __shared__ float a_s[C_DIM];
    __shared__ float p_s[N_DIM];
    __shared__ float red[256];

    const int bm  = blockIdx.x;
    const int b   = bm >> 4;
    const int tid = threadIdx.x;
    const float scale = rsqrtf((float)C_DIM);

    for (int c = tid; c < C_DIM; c += 256)
        a_s[c] = A[(size_t)bm * C_DIM + c];
    __syncthreads();

    const float* Kb = Kmat + (size_t)b * N_DIM * C_DIM;
#pragma unroll
    for (int i = 0; i < 4; i++) {
        int n = tid + i * 256;
        const float4* krow = reinterpret_cast<const float4*>(Kb + (size_t)n * C_DIM);
        float dot = 0.f;
#pragma unroll 4
        for (int c4 = 0; c4 < C_DIM / 4; c4++) {
            float4 kv = krow[c4];
            dot += a_s[c4 * 4 + 0] * kv.x + a_s[c4 * 4 + 1] * kv.y
                 + a_s[c4 * 4 + 2] * kv.z + a_s[c4 * 4 + 3] * kv.w;
        }
        p_s[n] = dot * scale;
    }
    __syncthreads();

    float lmax = -INFINITY;
#pragma unroll
    for (int i = 0; i < 4; i++) lmax = fmaxf(lmax, p_s[tid + i * 256]);
    red[tid] = lmax; __syncthreads();
    for (int s = 128; s > 0; s >>= 1) {
        if (tid < s) red[tid] = fmaxf(red[tid], red[tid + s]);
        __syncthreads();
    }
    const float mx = red[0];
    __syncthreads();

    float lsum = 0.f;
#pragma unroll
    for (int i = 0; i < 4; i++) {
        int n = tid + i * 256;
        float e = __expf(p_s[n] - mx);
        p_s[n] = e;
        lsum += e;
    }
    red[tid] = lsum; __syncthreads();
    for (int s = 128; s > 0; s >>= 1) {
        if (tid < s) red[tid] += red[tid + s];
        __syncthreads();
    }
    const float inv = 1.0f / red[0];

    const float* Vb = V + (size_t)b * N_DIM * C_DIM;
    float acc0 = 0.f, acc1 = 0.f;
    for (int n = 0; n < N_DIM; n++) {
        float p = p_s[n];
        const float* vrow = Vb + (size_t)n * C_DIM;
        acc0 = fmaf(p, vrow[tid],        acc0);
        acc1 = fmaf(p, vrow[tid + 256],  acc1);
    }
    AF[(size_t)bm * C_DIM + tid]       = acc0 * inv;
    AF[(size_t)bm * C_DIM + tid + 256] = acc1 * inv;
}

// ---------------- agent attn (writes combined bf16 [hi|lo] rows) ----------------
__global__ __launch_bounds__(512)
void agent_attn_kernel(const float* __restrict__ Q, const float* __restrict__ A,
                       const float* __restrict__ AF, __nv_bfloat16* __restrict__ Ats)
{
    __shared__ float af_s[M_AG][C_DIM];

    const int b    = blockIdx.y;
    const int n0   = blockIdx.x * 16;
    const int tid  = threadIdx.x;
    const int warp = tid >> 5;
    const int lane = tid & 31;
    const float scale = rsqrtf((float)C_DIM);

    const float* AFb = AF + (size_t)b * M_AG * C_DIM;
    for (int i = tid; i < M_AG * C_DIM; i += 512)
        (&af_s[0][0])[i] = AFb[i];
    __syncthreads();

    const int n = n0 + warp;
    const float* qrow = Q + ((size_t)b * N_DIM + n) * C_DIM;
    float q[16];
#pragma unroll
    for (int k = 0; k < 16; k++) q[k] = qrow[lane + 32 * k];

    const float* Ab = A + (size_t)b * M_AG * C_DIM;
    float lg[16];
#pragma unroll
    for (int m = 0; m < M_AG; m++) {
        const float* arow = Ab + (size_t)m * C_DIM;
        float p = 0.f;
#pragma unroll
        for (int k = 0; k < 16; k++) p = fmaf(q[k], arow[lane + 32 * k], p);
#pragma unroll
        for (int off = 16; off > 0; off >>= 1)
            p += __shfl_xor_sync(0xffffffffu, p, off);
        lg[m] = p * scale;
    }

    float mx = lg[0];
#pragma unroll
    for (int m = 1; m < M_AG; m++) mx = fmaxf(mx, lg[m]);
    float s = 0.f;
#pragma unroll
    for (int m = 0; m < M_AG; m++) { lg[m] = __expf(lg[m] - mx); s += lg[m]; }
    const float inv = 1.0f / s;

    __nv_bfloat16* orow = Ats + ((size_t)b * N_DIM + n) * K2;
#pragma unroll
    for (int k = 0; k < 16; k++) {
        int c = lane + 32 * k;
        float o = 0.f;
#pragma unroll
        for (int m = 0; m < M_AG; m++) o = fmaf(lg[m], af_s[m][c], o);
        o *= inv;
        __nv_bfloat16 h = __float2bfloat16(o);
        orow[c]       = h;
        orow[c + 512] = __float2bfloat16(o - __bfloat162float(h));
    }
}

// ---------------- launch ----------------
extern "C" void kernel_launch(void* const* d_in, const int* in_sizes, int n_in,
                              void* d_out, int out_size)
{
    const float* x  = (const float*)d_in[0];
    const float* Wq = (const float*)d_in[1];
    const float* bq = (const float*)d_in[2];
    const float* Wk = (const float*)d_in[3];
    const float* bk = (const float*)d_in[4];
    const float* Wv = (const float*)d_in[5];
    const float* bv = (const float*)d_in[6];
    const float* Wo = (const float*)d_in[7];
    const float* bo = (const float*)d_in[8];
    float* out = (float*)d_out;

    float *Q, *K, *V, *A, *AF;
    __nv_bfloat16 *Xs, *Ats, *Ws;
    cudaGetSymbolAddress((void**)&Q,   g_Q);
    cudaGetSymbolAddress((void**)&K,   g_K);
    cudaGetSymbolAddress((void**)&V,   g_V);
    cudaGetSymbolAddress((void**)&A,   g_A);
    cudaGetSymbolAddress((void**)&AF,  g_AF);
    cudaGetSymbolAddress((void**)&Xs,  g_Xs);
    cudaGetSymbolAddress((void**)&Ats, g_Ats);
    cudaGetSymbolAddress((void**)&Ws,  g_Ws);

    static int smem_set = 0;
    if (!smem_set) {
        cudaFuncSetAttribute(gemm_mma, cudaFuncAttributeMaxDynamicSharedMemorySize, GEMM_SMEM);
        smem_set = 1;
    }

    const size_t WSZ = (size_t)C_DIM * K2;      // combined W rows
    const int nq_x = R_DIM * C_DIM / 4;
    const int nq_w = C_DIM * C_DIM / 4;

    split_kernel<<<nq_x / 256, 256>>>(x,  Xs, nq_x);
    split_kernel<<<nq_w / 256, 256>>>(Wq, Ws + 0 * WSZ, nq_w);
    split_kernel<<<nq_w / 256, 256>>>(Wk, Ws + 1 * WSZ, nq_w);
    split_kernel<<<nq_w / 256, 256>>>(Wv, Ws + 2 * WSZ, nq_w);
    split_kernel<<<nq_w / 256, 256>>>(Wo, Ws + 3 * WSZ, nq_w);

    dim3 gg(C_DIM / 128, R_DIM / 128);          // (4, 512)
    gemm_mma<<<gg, 256, GEMM_SMEM>>>(Xs, Ws + 0 * WSZ, bq, Q);
    gemm_mma<<<gg, 256, GEMM_SMEM>>>(Xs, Ws + 1 * WSZ, bk, K);
    gemm_mma<<<gg, 256, GEMM_SMEM>>>(Xs, Ws + 2 * WSZ, bv, V);

    pool_kernel<<<B_DIM * M_AG, C_DIM>>>(Q, A);
    agent_features_kernel<<<B_DIM * M_AG, 256>>>(A, K, V, AF);

    dim3 attn_grid(N_DIM / 16, B_DIM);
    agent_attn_kernel<<<attn_grid, 512>>>(Q, A, AF, Ats);

    gemm_mma<<<gg, 256, GEMM_SMEM>>>(Ats, Ws + 3 * WSZ, bo, out);
}